// round 1
// baseline (speedup 1.0000x reference)
#include <cuda_runtime.h>
#include <cstdint>

#define EMB   768
#define NHEAD 8
#define HD    96
#define BATCH 2
#define SEQ   4096
#define MROWS (BATCH * SEQ)          // 8192
#define QKVN  (4 * EMB)              // 3072

// ---------------- scratch (static device globals; no allocs allowed) -------
__device__ float g_q[BATCH * NHEAD * SEQ * HD];   // 6.29M floats each
__device__ float g_k[BATCH * NHEAD * SEQ * HD];
__device__ float g_v[BATCH * NHEAD * SEQ * HD];
__device__ float g_r[BATCH * NHEAD * SEQ * HD];
__device__ float g_att[MROWS * EMB];

// ===========================================================================
// 128x128x8 split-tile fp32 SGEMM, 256 threads, 8x8 micro-tile per thread
// (rows {tr*4, tr*4+64}, cols {tc*4, tc*4+64}).
// ===========================================================================

// ---- GEMM 1: X[8192,768] @ W[768,3072] + b  -> scatter to q/k/v/r ---------
__global__ __launch_bounds__(256, 2)
void sgemm_qkv(const float* __restrict__ A, const float* __restrict__ B,
               const float* __restrict__ bias)
{
    __shared__ float As[8][132];   // transposed A tile, padded
    __shared__ float Bs[8][128];

    const int K = EMB, N = QKVN;
    const int m0 = blockIdx.y * 128;
    const int n0 = blockIdx.x * 128;
    const int tid = threadIdx.x;
    const int tr = tid >> 4, tc = tid & 15;

    float c[8][8];
#pragma unroll
    for (int i = 0; i < 8; i++)
#pragma unroll
        for (int j = 0; j < 8; j++) c[i][j] = 0.f;

    const int arow = tid >> 1, akq = (tid & 1) * 4;
    const int brow = tid >> 5, bcol = (tid & 31) * 4;

    for (int k0 = 0; k0 < K; k0 += 8) {
        float4 av = *(const float4*)(A + (size_t)(m0 + arow) * K + k0 + akq);
        As[akq + 0][arow] = av.x;
        As[akq + 1][arow] = av.y;
        As[akq + 2][arow] = av.z;
        As[akq + 3][arow] = av.w;
        *(float4*)(&Bs[brow][bcol]) =
            *(const float4*)(B + (size_t)(k0 + brow) * N + n0 + bcol);
        __syncthreads();
#pragma unroll
        for (int kk = 0; kk < 8; kk++) {
            float a[8], b[8];
            *(float4*)(a)     = *(const float4*)(&As[kk][tr * 4]);
            *(float4*)(a + 4) = *(const float4*)(&As[kk][tr * 4 + 64]);
            *(float4*)(b)     = *(const float4*)(&Bs[kk][tc * 4]);
            *(float4*)(b + 4) = *(const float4*)(&Bs[kk][tc * 4 + 64]);
#pragma unroll
            for (int i = 0; i < 8; i++)
#pragma unroll
                for (int j = 0; j < 8; j++) c[i][j] += a[i] * b[j];
        }
        __syncthreads();
    }

    // epilogue: bias + scatter.  col = h*384 + d*4 + qkvr
#pragma unroll
    for (int i = 0; i < 8; i++) {
        int rowg = m0 + ((i < 4) ? tr * 4 + i : 64 + tr * 4 + (i - 4));
        int b_  = rowg >> 12;          // /4096
        int n   = rowg & 4095;
#pragma unroll
        for (int j = 0; j < 8; j++) {
            int colg = n0 + ((j < 4) ? tc * 4 + j : 64 + tc * 4 + (j - 4));
            float val = c[i][j] + bias[colg];
            int qk   = colg & 3;
            int rest = colg >> 2;
            int d    = rest % 96;
            int h    = rest / 96;
            size_t dst = ((size_t)(b_ * NHEAD + h) * SEQ + n) * HD + d;
            float* t = (qk == 0) ? g_q : (qk == 1) ? g_k : (qk == 2) ? g_v : g_r;
            t[dst] = val;
        }
    }
}

// ---- GEMM 2: att[8192,768] @ Wp[768,768] + bp -> out ----------------------
__global__ __launch_bounds__(256, 2)
void sgemm_proj(const float* __restrict__ A, const float* __restrict__ B,
                const float* __restrict__ bias, float* __restrict__ out)
{
    __shared__ float As[8][132];
    __shared__ float Bs[8][128];

    const int K = EMB, N = EMB;
    const int m0 = blockIdx.y * 128;
    const int n0 = blockIdx.x * 128;
    const int tid = threadIdx.x;
    const int tr = tid >> 4, tc = tid & 15;

    float c[8][8];
#pragma unroll
    for (int i = 0; i < 8; i++)
#pragma unroll
        for (int j = 0; j < 8; j++) c[i][j] = 0.f;

    const int arow = tid >> 1, akq = (tid & 1) * 4;
    const int brow = tid >> 5, bcol = (tid & 31) * 4;

    for (int k0 = 0; k0 < K; k0 += 8) {
        float4 av = *(const float4*)(A + (size_t)(m0 + arow) * K + k0 + akq);
        As[akq + 0][arow] = av.x;
        As[akq + 1][arow] = av.y;
        As[akq + 2][arow] = av.z;
        As[akq + 3][arow] = av.w;
        *(float4*)(&Bs[brow][bcol]) =
            *(const float4*)(B + (size_t)(k0 + brow) * N + n0 + bcol);
        __syncthreads();
#pragma unroll
        for (int kk = 0; kk < 8; kk++) {
            float a[8], b[8];
            *(float4*)(a)     = *(const float4*)(&As[kk][tr * 4]);
            *(float4*)(a + 4) = *(const float4*)(&As[kk][tr * 4 + 64]);
            *(float4*)(b)     = *(const float4*)(&Bs[kk][tc * 4]);
            *(float4*)(b + 4) = *(const float4*)(&Bs[kk][tc * 4 + 64]);
#pragma unroll
            for (int i = 0; i < 8; i++)
#pragma unroll
                for (int j = 0; j < 8; j++) c[i][j] += a[i] * b[j];
        }
        __syncthreads();
    }

#pragma unroll
    for (int i = 0; i < 8; i++) {
        int rowg = m0 + ((i < 4) ? tr * 4 + i : 64 + tr * 4 + (i - 4));
#pragma unroll
        for (int j = 0; j < 8; j++) {
            int colg = n0 + ((j < 4) ? tc * 4 + j : 64 + tc * 4 + (j - 4));
            out[(size_t)rowg * EMB + colg] = c[i][j] + bias[colg];
        }
    }
}

// ===========================================================================
// Flash-style attention.  grid = (SEQ/64, BATCH*NHEAD), 256 threads.
// Per thread: S frag 4x4 (rows ty*4.., cols tx*4..), O frag 4x6 (cols tx*6..)
// Ks is XOR-swizzled (float4 col ^ (row>>2)&7) so QK^T smem loads are <=2-way.
// Softmax output is divided by sqrt(EMB) (reference's unusual order), then
// gated by r, stored directly to (b, n, h*96+d) layout for the final GEMM.
// ===========================================================================
#define QS_STRIDE 100
#define VS_STRIDE 100
#define PS_STRIDE 65
#define ATT_SMEM_BYTES ((64 * QS_STRIDE + 64 * 96 + 64 * VS_STRIDE + 64 * PS_STRIDE) * 4)

__global__ __launch_bounds__(256, 2)
void attn_kernel(const float* __restrict__ gq, const float* __restrict__ gk,
                 const float* __restrict__ gv, const float* __restrict__ gr,
                 float* __restrict__ gatt)
{
    extern __shared__ float sm[];
    float* Qs = sm;                       // [64][100]
    float* Ks = Qs + 64 * QS_STRIDE;      // [64][96], swizzled
    float* Vs = Ks + 64 * 96;             // [64][100]
    float* Ps = Vs + 64 * VS_STRIDE;      // [64][65]

    const int tid = threadIdx.x;
    const int ty = tid >> 4, tx = tid & 15;
    const int bh = blockIdx.y;
    const int qb = blockIdx.x;
    const size_t base = (size_t)bh * SEQ * HD;
    const float* qptr = gq + base + (size_t)qb * 64 * HD;

    // load Q tile [64][96] -> Qs (stride 100)
#pragma unroll
    for (int i = 0; i < 6; i++) {
        int u = i * 256 + tid;            // 1536 float4s
        int row = u / 24, c4 = u % 24;
        *(float4*)(Qs + row * QS_STRIDE + c4 * 4) =
            *(const float4*)(qptr + row * HD + c4 * 4);
    }

    float m[4], l[4], acc[4][6];
#pragma unroll
    for (int i = 0; i < 4; i++) {
        m[i] = -1e30f; l[i] = 0.f;
#pragma unroll
        for (int c0 = 0; c0 < 6; c0++) acc[i][c0] = 0.f;
    }

    const int r0 = ty * 4, c0 = tx * 4, oc0 = tx * 6;

    for (int kb = 0; kb < SEQ / 64; kb++) {
        __syncthreads();                  // K/V/P buffers free (and Q visible)
        const float* kptr = gk + base + (size_t)kb * 64 * HD;
        const float* vptr = gv + base + (size_t)kb * 64 * HD;
#pragma unroll
        for (int i = 0; i < 6; i++) {
            int u = i * 256 + tid;
            int row = u / 24, c4 = u % 24;
            int p = c4 ^ ((row >> 2) & 7);   // swizzle K
            *(float4*)(Ks + row * 96 + p * 4) =
                *(const float4*)(kptr + row * HD + c4 * 4);
            *(float4*)(Vs + row * VS_STRIDE + c4 * 4) =
                *(const float4*)(vptr + row * HD + c4 * 4);
        }
        __syncthreads();

        // S = Q K^T fragment
        float s[4][4];
#pragma unroll
        for (int i = 0; i < 4; i++)
#pragma unroll
            for (int j = 0; j < 4; j++) s[i][j] = 0.f;

#pragma unroll 4
        for (int d4 = 0; d4 < 24; d4++) {
            int d = d4 * 4;
            int sw = (d4 ^ (tx & 7)) * 4;
            float4 qv[4], kv[4];
#pragma unroll
            for (int i = 0; i < 4; i++)
                qv[i] = *(const float4*)(Qs + (r0 + i) * QS_STRIDE + d);
#pragma unroll
            for (int j = 0; j < 4; j++)
                kv[j] = *(const float4*)(Ks + (c0 + j) * 96 + sw);
#pragma unroll
            for (int i = 0; i < 4; i++)
#pragma unroll
                for (int j = 0; j < 4; j++)
                    s[i][j] += qv[i].x * kv[j].x + qv[i].y * kv[j].y +
                               qv[i].z * kv[j].z + qv[i].w * kv[j].w;
        }

        // online softmax update (row stats reduced across the 16 tx lanes)
#pragma unroll
        for (int i = 0; i < 4; i++) {
            float bm = fmaxf(fmaxf(s[i][0], s[i][1]), fmaxf(s[i][2], s[i][3]));
#pragma unroll
            for (int off = 8; off >= 1; off >>= 1)
                bm = fmaxf(bm, __shfl_xor_sync(0xffffffffu, bm, off));
            float mn = fmaxf(m[i], bm);
            float psum = 0.f;
#pragma unroll
            for (int j = 0; j < 4; j++) {
                float p = __expf(s[i][j] - mn);
                Ps[(r0 + i) * PS_STRIDE + c0 + j] = p;
                psum += p;
            }
#pragma unroll
            for (int off = 8; off >= 1; off >>= 1)
                psum += __shfl_xor_sync(0xffffffffu, psum, off);
            float scale = __expf(m[i] - mn);
            l[i] = l[i] * scale + psum;
            m[i] = mn;
#pragma unroll
            for (int c1 = 0; c1 < 6; c1++) acc[i][c1] *= scale;
        }
        __syncthreads();                  // Ps complete

        // O += P @ V
#pragma unroll 4
        for (int j = 0; j < 64; j++) {
            float p0 = Ps[(r0 + 0) * PS_STRIDE + j];
            float p1 = Ps[(r0 + 1) * PS_STRIDE + j];
            float p2 = Ps[(r0 + 2) * PS_STRIDE + j];
            float p3 = Ps[(r0 + 3) * PS_STRIDE + j];
            const float* vrow = Vs + j * VS_STRIDE + oc0;
            float2 v01 = *(const float2*)(vrow);
            float2 v23 = *(const float2*)(vrow + 2);
            float2 v45 = *(const float2*)(vrow + 4);
            float vv[6] = {v01.x, v01.y, v23.x, v23.y, v45.x, v45.y};
#pragma unroll
            for (int c1 = 0; c1 < 6; c1++) {
                acc[0][c1] += p0 * vv[c1];
                acc[1][c1] += p1 * vv[c1];
                acc[2][c1] += p2 * vv[c1];
                acc[3][c1] += p3 * vv[c1];
            }
        }
    }

    // epilogue: /l, * 1/sqrt(768), gate by r, store (b, n, h*96+d)
    const float inv_sqrt_emb = 0.03608439182435161f;
    const int b_ = bh >> 3, h = bh & 7;
#pragma unroll
    for (int i = 0; i < 4; i++) {
        int n = qb * 64 + r0 + i;
        float linv = inv_sqrt_emb / l[i];
#pragma unroll
        for (int c1 = 0; c1 < 6; c1++) {
            int d = oc0 + c1;
            float val = acc[i][c1] * linv * gr[base + (size_t)n * HD + d];
            gatt[((size_t)(b_ * SEQ + n)) * EMB + h * HD + d] = val;
        }
    }
}

// ===========================================================================
extern "C" void kernel_launch(void* const* d_in, const int* in_sizes, int n_in,
                              void* d_out, int out_size)
{
    const float* x      = (const float*)d_in[0];
    const float* w_qkvr = (const float*)d_in[1];
    const float* b_qkvr = (const float*)d_in[2];
    const float* w_proj = (const float*)d_in[3];
    const float* b_proj = (const float*)d_in[4];
    float* out = (float*)d_out;

    cudaFuncSetAttribute(attn_kernel,
                         cudaFuncAttributeMaxDynamicSharedMemorySize,
                         ATT_SMEM_BYTES);

    float *gq, *gk, *gv, *gr, *gatt;
    cudaGetSymbolAddress((void**)&gq, g_q);
    cudaGetSymbolAddress((void**)&gk, g_k);
    cudaGetSymbolAddress((void**)&gv, g_v);
    cudaGetSymbolAddress((void**)&gr, g_r);
    cudaGetSymbolAddress((void**)&gatt, g_att);

    sgemm_qkv<<<dim3(QKVN / 128, MROWS / 128), 256>>>(x, w_qkvr, b_qkvr);
    attn_kernel<<<dim3(SEQ / 64, BATCH * NHEAD), 256, ATT_SMEM_BYTES>>>(
        gq, gk, gv, gr, gatt);
    sgemm_proj<<<dim3(EMB / 128, MROWS / 128), 256>>>(gatt, w_proj, b_proj, out);
}

// round 2
// speedup vs baseline: 1.3884x; 1.3884x over previous
#include <cuda_runtime.h>
#include <cstdint>

#define EMB   768
#define NHEAD 8
#define HD    96
#define BATCH 2
#define SEQ   4096
#define MROWS (BATCH * SEQ)          // 8192
#define QKVN  (4 * EMB)              // 3072

// ---------------- scratch (static device globals; no allocs allowed) -------
__device__ float g_q[BATCH * NHEAD * SEQ * HD];
__device__ float g_k[BATCH * NHEAD * SEQ * HD];
__device__ float g_v[BATCH * NHEAD * SEQ * HD];
__device__ float g_r[BATCH * NHEAD * SEQ * HD];
__device__ float g_att[MROWS * EMB];

// ---------------- tf32 helpers ---------------------------------------------
__device__ __forceinline__ uint32_t f2tf(float x) {
    uint32_t r;
    asm("cvt.rna.tf32.f32 %0, %1;" : "=r"(r) : "f"(x));
    return r;
}

// D += A(tf32) * B(tf32), m16n8k8, fp32 accumulate
__device__ __forceinline__ void mma8(float* d,
                                     uint32_t a0, uint32_t a1, uint32_t a2, uint32_t a3,
                                     uint32_t b0, uint32_t b1) {
    asm volatile(
        "mma.sync.aligned.m16n8k8.row.col.f32.tf32.tf32.f32 "
        "{%0,%1,%2,%3}, {%4,%5,%6,%7}, {%8,%9}, {%0,%1,%2,%3};"
        : "+f"(d[0]), "+f"(d[1]), "+f"(d[2]), "+f"(d[3])
        : "r"(a0), "r"(a1), "r"(a2), "r"(a3), "r"(b0), "r"(b1));
}

// ===========================================================================
// TF32 tensor-core GEMM, BM=128 BN=128 BK=16, 256 threads (8 warps 2x4),
// warp tile 64x32 (m-tiles 4, n-tiles 4).
// COMP=1: 3-product compensated tf32 (~fp32 accuracy). COMP=0: plain tf32.
// EPI=0: bias + qkvr scatter into g_q/g_k/g_v/g_r. EPI=1: bias + store to out.
// As is stored K-major [16][136] so A-frag LDS is conflict-free; Bs [16][136].
// ===========================================================================
template <int COMP, int EPI>
__global__ __launch_bounds__(256, 1)
void gemm_tf32(const float* __restrict__ A, const float* __restrict__ B,
               const float* __restrict__ bias, float* __restrict__ out, int N)
{
    __shared__ float As[16 * 136];   // As[k][m]
    __shared__ float Bs[16 * 136];   // Bs[k][n]

    const int K  = EMB;
    const int m0 = blockIdx.y * 128;
    const int n0 = blockIdx.x * 128;
    const int tid  = threadIdx.x;
    const int warp = tid >> 5;
    const int lane = tid & 31;
    const int g = lane >> 2, q = lane & 3;
    const int wm0 = (warp >> 2) * 64;     // 0 or 64
    const int wn0 = (warp & 3) * 32;      // 0,32,64,96

    float acc[4][4][4];
#pragma unroll
    for (int i = 0; i < 4; i++)
#pragma unroll
        for (int j = 0; j < 4; j++)
#pragma unroll
            for (int e = 0; e < 4; e++) acc[i][j][e] = 0.f;

    for (int k0 = 0; k0 < K; k0 += 16) {
        // load A tile (transpose into As[k][m]) and B tile
#pragma unroll
        for (int it = 0; it < 2; it++) {
            int u = it * 256 + tid;              // 512 float4s each
            int arow = u >> 2, ac4 = u & 3;
            float4 av = *(const float4*)(A + (size_t)(m0 + arow) * K + k0 + ac4 * 4);
            As[(ac4 * 4 + 0) * 136 + arow] = av.x;
            As[(ac4 * 4 + 1) * 136 + arow] = av.y;
            As[(ac4 * 4 + 2) * 136 + arow] = av.z;
            As[(ac4 * 4 + 3) * 136 + arow] = av.w;
            int brow = u >> 5, bc4 = u & 31;
            *(float4*)(&Bs[brow * 136 + bc4 * 4]) =
                *(const float4*)(B + (size_t)(k0 + brow) * N + n0 + bc4 * 4);
        }
        __syncthreads();

#pragma unroll
        for (int kk = 0; kk < 16; kk += 8) {
            uint32_t ahi[4][4], alo[4][4];
#pragma unroll
            for (int mt = 0; mt < 4; mt++) {
                int mrow = wm0 + mt * 16 + g;
                float a0 = As[(kk + q) * 136 + mrow];
                float a1 = As[(kk + q) * 136 + mrow + 8];
                float a2 = As[(kk + q + 4) * 136 + mrow];
                float a3 = As[(kk + q + 4) * 136 + mrow + 8];
                ahi[mt][0] = f2tf(a0); ahi[mt][1] = f2tf(a1);
                ahi[mt][2] = f2tf(a2); ahi[mt][3] = f2tf(a3);
                if (COMP) {
                    alo[mt][0] = f2tf(a0 - __uint_as_float(ahi[mt][0]));
                    alo[mt][1] = f2tf(a1 - __uint_as_float(ahi[mt][1]));
                    alo[mt][2] = f2tf(a2 - __uint_as_float(ahi[mt][2]));
                    alo[mt][3] = f2tf(a3 - __uint_as_float(ahi[mt][3]));
                }
            }
            uint32_t bhi[4][2], blo[4][2];
#pragma unroll
            for (int nt = 0; nt < 4; nt++) {
                int ncol = wn0 + nt * 8 + g;
                float b0 = Bs[(kk + q) * 136 + ncol];
                float b1 = Bs[(kk + q + 4) * 136 + ncol];
                bhi[nt][0] = f2tf(b0); bhi[nt][1] = f2tf(b1);
                if (COMP) {
                    blo[nt][0] = f2tf(b0 - __uint_as_float(bhi[nt][0]));
                    blo[nt][1] = f2tf(b1 - __uint_as_float(bhi[nt][1]));
                }
            }
#pragma unroll
            for (int mt = 0; mt < 4; mt++)
#pragma unroll
                for (int nt = 0; nt < 4; nt++) {
                    mma8(acc[mt][nt], ahi[mt][0], ahi[mt][1], ahi[mt][2], ahi[mt][3],
                         bhi[nt][0], bhi[nt][1]);
                    if (COMP) {
                        mma8(acc[mt][nt], alo[mt][0], alo[mt][1], alo[mt][2], alo[mt][3],
                             bhi[nt][0], bhi[nt][1]);
                        mma8(acc[mt][nt], ahi[mt][0], ahi[mt][1], ahi[mt][2], ahi[mt][3],
                             blo[nt][0], blo[nt][1]);
                    }
                }
        }
        __syncthreads();
    }

    // epilogue
#pragma unroll
    for (int mt = 0; mt < 4; mt++)
#pragma unroll
        for (int nt = 0; nt < 4; nt++)
#pragma unroll
            for (int e = 0; e < 4; e++) {
                int rowg = m0 + wm0 + mt * 16 + g + ((e >= 2) ? 8 : 0);
                int colg = n0 + wn0 + nt * 8 + 2 * q + (e & 1);
                float val = acc[mt][nt][e] + bias[colg];
                if (EPI == 1) {
                    out[(size_t)rowg * N + colg] = val;
                } else {
                    int b_   = rowg >> 12;
                    int n    = rowg & 4095;
                    int qk   = colg & 3;
                    int rest = colg >> 2;
                    int d    = rest % 96;
                    int h    = rest / 96;
                    size_t dst = ((size_t)(b_ * NHEAD + h) * SEQ + n) * HD + d;
                    float* t = (qk == 0) ? g_q : (qk == 1) ? g_k : (qk == 2) ? g_v : g_r;
                    t[dst] = val;
                }
            }
}

// ===========================================================================
// Flash attention with tf32 mma.  grid (SEQ/128, B*H), 256 threads (8 warps),
// each warp owns 16 q-rows; k-blocks of 64 keys.
// QK^T: 3-product compensated tf32 (logit path).  PV: plain tf32.
// smem strides chosen so every fragment LDS pattern is bank-conflict-free.
// ===========================================================================
#define QS_OFF  0                         // Qs[128][104] fp32
#define KHI_OFF (QS_OFF + 128 * 104)      // Khi[64][104]  (K[n][k], tf32 hi)
#define KLO_OFF (KHI_OFF + 64 * 104)      // Klo[64][104]
#define VS_OFF  (KLO_OFF + 64 * 104)      // Vs[64][104]   (V[k][n], tf32-rounded)
#define PS_OFF  (VS_OFF + 64 * 104)       // Ps[128][72]   (tf32-rounded)
#define ATT_SMEM_FLOATS (PS_OFF + 128 * 72)
#define ATT_SMEM_BYTES  (ATT_SMEM_FLOATS * 4)

__global__ __launch_bounds__(256, 1)
void attn_kernel(const float* __restrict__ gq, const float* __restrict__ gk,
                 const float* __restrict__ gv, const float* __restrict__ gr,
                 float* __restrict__ gatt)
{
    extern __shared__ float sm[];
    float* Qs  = sm + QS_OFF;
    float* Khi = sm + KHI_OFF;
    float* Klo = sm + KLO_OFF;
    float* Vs  = sm + VS_OFF;
    float* Ps  = sm + PS_OFF;

    const int tid  = threadIdx.x;
    const int warp = tid >> 5;
    const int lane = tid & 31;
    const int g = lane >> 2, q = lane & 3;
    const int qr0 = warp * 16;                 // warp's local q-row base

    const int bh = blockIdx.y;
    const int qb = blockIdx.x;
    const size_t base = (size_t)bh * SEQ * HD;
    const float* qptr = gq + base + (size_t)qb * 128 * HD;

    // load Q tile [128][96] fp32
#pragma unroll
    for (int i = 0; i < 12; i++) {
        int u = i * 256 + tid;                 // 3072 float4s
        int row = u / 24, c4 = u % 24;
        *(float4*)(Qs + row * 104 + c4 * 4) =
            *(const float4*)(qptr + row * HD + c4 * 4);
    }

    float o[12][4];
    float m_a = -1e30f, m_b = -1e30f, l_a = 0.f, l_b = 0.f;
#pragma unroll
    for (int nt = 0; nt < 12; nt++)
#pragma unroll
        for (int e = 0; e < 4; e++) o[nt][e] = 0.f;

    for (int kb = 0; kb < SEQ / 64; kb++) {
        __syncthreads();                       // prev K/V fully consumed (and Q ready)
        const float* kptr = gk + base + (size_t)kb * 64 * HD;
        const float* vptr = gv + base + (size_t)kb * 64 * HD;
#pragma unroll
        for (int i = 0; i < 6; i++) {
            int u = i * 256 + tid;             // 1536 float4s
            int row = u / 24, c4 = u % 24;
            float4 kv = *(const float4*)(kptr + row * HD + c4 * 4);
            float4 vv = *(const float4*)(vptr + row * HD + c4 * 4);
            uint32_t h0 = f2tf(kv.x), h1 = f2tf(kv.y), h2 = f2tf(kv.z), h3 = f2tf(kv.w);
            float4 khi4 = make_float4(__uint_as_float(h0), __uint_as_float(h1),
                                      __uint_as_float(h2), __uint_as_float(h3));
            float4 klo4 = make_float4(
                __uint_as_float(f2tf(kv.x - khi4.x)), __uint_as_float(f2tf(kv.y - khi4.y)),
                __uint_as_float(f2tf(kv.z - khi4.z)), __uint_as_float(f2tf(kv.w - khi4.w)));
            *(float4*)(Khi + row * 104 + c4 * 4) = khi4;
            *(float4*)(Klo + row * 104 + c4 * 4) = klo4;
            float4 vhi4 = make_float4(__uint_as_float(f2tf(vv.x)), __uint_as_float(f2tf(vv.y)),
                                      __uint_as_float(f2tf(vv.z)), __uint_as_float(f2tf(vv.w)));
            *(float4*)(Vs + row * 104 + c4 * 4) = vhi4;
        }
        __syncthreads();

        // ---- S = Q K^T (compensated tf32), warp tile 16x64, 8 n-tiles ----
        float s[8][4];
#pragma unroll
        for (int nt = 0; nt < 8; nt++)
#pragma unroll
            for (int e = 0; e < 4; e++) s[nt][e] = 0.f;

#pragma unroll
        for (int ks = 0; ks < 12; ks++) {
            int kc = ks * 8;
            float a0 = Qs[(qr0 + g) * 104 + kc + q];
            float a1 = Qs[(qr0 + g + 8) * 104 + kc + q];
            float a2 = Qs[(qr0 + g) * 104 + kc + q + 4];
            float a3 = Qs[(qr0 + g + 8) * 104 + kc + q + 4];
            uint32_t ah0 = f2tf(a0), ah1 = f2tf(a1), ah2 = f2tf(a2), ah3 = f2tf(a3);
            uint32_t al0 = f2tf(a0 - __uint_as_float(ah0));
            uint32_t al1 = f2tf(a1 - __uint_as_float(ah1));
            uint32_t al2 = f2tf(a2 - __uint_as_float(ah2));
            uint32_t al3 = f2tf(a3 - __uint_as_float(ah3));
#pragma unroll
            for (int nt = 0; nt < 8; nt++) {
                int nrow = nt * 8 + g;
                uint32_t bh0 = __float_as_uint(Khi[nrow * 104 + kc + q]);
                uint32_t bh1 = __float_as_uint(Khi[nrow * 104 + kc + q + 4]);
                uint32_t bl0 = __float_as_uint(Klo[nrow * 104 + kc + q]);
                uint32_t bl1 = __float_as_uint(Klo[nrow * 104 + kc + q + 4]);
                mma8(s[nt], ah0, ah1, ah2, ah3, bh0, bh1);
                mma8(s[nt], al0, al1, al2, al3, bh0, bh1);
                mma8(s[nt], ah0, ah1, ah2, ah3, bl0, bl1);
            }
        }

        // ---- online softmax (fully intra-warp; rows g and g+8) ----
        float mx_a = -1e30f, mx_b = -1e30f;
#pragma unroll
        for (int nt = 0; nt < 8; nt++) {
            mx_a = fmaxf(mx_a, fmaxf(s[nt][0], s[nt][1]));
            mx_b = fmaxf(mx_b, fmaxf(s[nt][2], s[nt][3]));
        }
        mx_a = fmaxf(mx_a, __shfl_xor_sync(0xffffffffu, mx_a, 1));
        mx_a = fmaxf(mx_a, __shfl_xor_sync(0xffffffffu, mx_a, 2));
        mx_b = fmaxf(mx_b, __shfl_xor_sync(0xffffffffu, mx_b, 1));
        mx_b = fmaxf(mx_b, __shfl_xor_sync(0xffffffffu, mx_b, 2));
        float nm_a = fmaxf(m_a, mx_a), nm_b = fmaxf(m_b, mx_b);
        float sc_a = __expf(m_a - nm_a), sc_b = __expf(m_b - nm_b);
        m_a = nm_a; m_b = nm_b;

        float sum_a = 0.f, sum_b = 0.f;
#pragma unroll
        for (int nt = 0; nt < 8; nt++) {
            float p0 = __expf(s[nt][0] - nm_a);
            float p1 = __expf(s[nt][1] - nm_a);
            float p2 = __expf(s[nt][2] - nm_b);
            float p3 = __expf(s[nt][3] - nm_b);
            sum_a += p0 + p1; sum_b += p2 + p3;
            int col = nt * 8 + 2 * q;
            Ps[(qr0 + g) * 72 + col]     = __uint_as_float(f2tf(p0));
            Ps[(qr0 + g) * 72 + col + 1] = __uint_as_float(f2tf(p1));
            Ps[(qr0 + g + 8) * 72 + col]     = __uint_as_float(f2tf(p2));
            Ps[(qr0 + g + 8) * 72 + col + 1] = __uint_as_float(f2tf(p3));
        }
        sum_a += __shfl_xor_sync(0xffffffffu, sum_a, 1);
        sum_a += __shfl_xor_sync(0xffffffffu, sum_a, 2);
        sum_b += __shfl_xor_sync(0xffffffffu, sum_b, 1);
        sum_b += __shfl_xor_sync(0xffffffffu, sum_b, 2);
        l_a = l_a * sc_a + sum_a;
        l_b = l_b * sc_b + sum_b;
#pragma unroll
        for (int nt = 0; nt < 12; nt++) {
            o[nt][0] *= sc_a; o[nt][1] *= sc_a;
            o[nt][2] *= sc_b; o[nt][3] *= sc_b;
        }
        __syncwarp();                          // Ps visible within warp

        // ---- O += P V (plain tf32), 12 n-tiles over d=96 ----
#pragma unroll
        for (int ks = 0; ks < 8; ks++) {
            int kc = ks * 8;
            uint32_t pa0 = __float_as_uint(Ps[(qr0 + g) * 72 + kc + q]);
            uint32_t pa1 = __float_as_uint(Ps[(qr0 + g + 8) * 72 + kc + q]);
            uint32_t pa2 = __float_as_uint(Ps[(qr0 + g) * 72 + kc + q + 4]);
            uint32_t pa3 = __float_as_uint(Ps[(qr0 + g + 8) * 72 + kc + q + 4]);
#pragma unroll
            for (int nt = 0; nt < 12; nt++) {
                uint32_t vb0 = __float_as_uint(Vs[(kc + q) * 104 + nt * 8 + g]);
                uint32_t vb1 = __float_as_uint(Vs[(kc + q + 4) * 104 + nt * 8 + g]);
                mma8(o[nt], pa0, pa1, pa2, pa3, vb0, vb1);
            }
        }
        __syncwarp();                          // done with Ps before next overwrite
    }

    // ---- epilogue: /l, *1/sqrt(768), gate by r, store (b, n, h*96+d) ----
    const float inv_sqrt_emb = 0.03608439182435161f;
    const int b_ = bh >> 3, h = bh & 7;
    const float li_a = inv_sqrt_emb / l_a;
    const float li_b = inv_sqrt_emb / l_b;
    const int n_a = qb * 128 + qr0 + g;
    const int n_b = n_a + 8;
#pragma unroll
    for (int nt = 0; nt < 12; nt++) {
        int d = nt * 8 + 2 * q;
        float ra0 = gr[base + (size_t)n_a * HD + d];
        float ra1 = gr[base + (size_t)n_a * HD + d + 1];
        float rb0 = gr[base + (size_t)n_b * HD + d];
        float rb1 = gr[base + (size_t)n_b * HD + d + 1];
        size_t oa = ((size_t)(b_ * SEQ + n_a)) * EMB + h * HD + d;
        size_t ob = ((size_t)(b_ * SEQ + n_b)) * EMB + h * HD + d;
        gatt[oa]     = o[nt][0] * li_a * ra0;
        gatt[oa + 1] = o[nt][1] * li_a * ra1;
        gatt[ob]     = o[nt][2] * li_b * rb0;
        gatt[ob + 1] = o[nt][3] * li_b * rb1;
    }
}

// ===========================================================================
extern "C" void kernel_launch(void* const* d_in, const int* in_sizes, int n_in,
                              void* d_out, int out_size)
{
    const float* x      = (const float*)d_in[0];
    const float* w_qkvr = (const float*)d_in[1];
    const float* b_qkvr = (const float*)d_in[2];
    const float* w_proj = (const float*)d_in[3];
    const float* b_proj = (const float*)d_in[4];
    float* out = (float*)d_out;

    cudaFuncSetAttribute(attn_kernel,
                         cudaFuncAttributeMaxDynamicSharedMemorySize,
                         ATT_SMEM_BYTES);

    float *gq, *gk, *gv, *gr, *gatt;
    cudaGetSymbolAddress((void**)&gq, g_q);
    cudaGetSymbolAddress((void**)&gk, g_k);
    cudaGetSymbolAddress((void**)&gv, g_v);
    cudaGetSymbolAddress((void**)&gr, g_r);
    cudaGetSymbolAddress((void**)&gatt, g_att);

    gemm_tf32<1, 0><<<dim3(QKVN / 128, MROWS / 128), 256>>>(
        x, w_qkvr, b_qkvr, nullptr, QKVN);
    attn_kernel<<<dim3(SEQ / 128, BATCH * NHEAD), 256, ATT_SMEM_BYTES>>>(
        gq, gk, gv, gr, gatt);
    gemm_tf32<0, 1><<<dim3(EMB / 128, MROWS / 128), 256>>>(
        gatt, w_proj, b_proj, out, EMB);
}